// round 16
// baseline (speedup 1.0000x reference)
#include <cuda_runtime.h>
#include <cuda_fp16.h>
#include <math.h>
#include <stdint.h>

#define BATCH 8
#define CHN 192
#define CH3 576
#define IMH 128
#define IMW 128
#define NPIX (IMH*IMW)         // 16384
#define NHEADS 4
#define HDIM 48
#define NORI 9
#define KHOG 32                // padded HOG K rows
#define KEXT (CHN+KHOG)        // 224
#define NSPLIT 16              // attn blocks (y)
#define NSLICE 32              // attnp slices (2 k-halves per block)
#define SPLITLEN (NPIX/NSPLIT) // 1024
#define PI_F 3.14159265358979323846f
#define NB 4                   // pipeline buffers (lookahead 2)

// ---- device scratch (no allocation allowed) ----
__device__ __half g_xh   [BATCH*CHN*NPIX];     // fp16 copy of x
__device__ __half g_wqkvh[CH3*CHN];            // fp16 W_qkv
__device__ __half g_qkv  [BATCH*CH3*NPIX];     // qkv (pre-dwconv), fp16
__device__ __half g_qkvdw[BATCH*CH3*NPIX];     // qkv (post-dwconv), fp16
__device__ __half g_wfh2 [BATCH*CHN*KEXT];     // [Wf | Wf@W_hog pad], row stride 224
__device__ __half g_hogwh[BATCH*KHOG*NPIX];    // fp16 hog bin weights; rows 9..31 zeroed
__device__ float g_zf   [BATCH*CHN*NORI];      // Z = blockdiag(attn) @ W_hog
__device__ float g_normp[2*BATCH*CHN*4];
__device__ float g_attnp[BATCH*NHEADS*NSLICE*HDIM*HDIM];

__device__ __forceinline__ uint32_t smem_u32(const void* p) {
    return (uint32_t)__cvta_generic_to_shared(p);
}
__device__ __forceinline__ void cp_async16(uint32_t dst, const void* src) {
    asm volatile("cp.async.cg.shared.global [%0], [%1], 16;\n" :: "r"(dst), "l"(src));
}
__device__ __forceinline__ void cp_commit() {
    asm volatile("cp.async.commit_group;\n");
}
__device__ __forceinline__ void cp_wait2() {
    asm volatile("cp.async.wait_group 2;\n");
}
__device__ __forceinline__ float fast_sqrtf(float x) {
    float r; asm("sqrt.approx.f32 %0, %1;" : "=f"(r) : "f"(x)); return r;
}
__device__ __forceinline__ float fast_atan2f(float y, float x) {
    float ax = fabsf(x), ay = fabsf(y);
    float mx = fmaxf(ax, ay), mn = fminf(ax, ay);
    float a = __fdividef(mn, mx);
    float s = a * a;
    float r = -0.0117212f;
    r = fmaf(r, s,  0.05265332f);
    r = fmaf(r, s, -0.11643287f);
    r = fmaf(r, s,  0.19354346f);
    r = fmaf(r, s, -0.33262347f);
    r = fmaf(r, s,  0.99997726f);
    r = r * a;
    if (ay > ax) r = 1.57079632679f - r;
    if (x < 0.f) r = PI_F - r;
    return y < 0.f ? -r : r;
}

#define LDSM_X4(r0, r1, r2, r3, addr) \
    asm volatile("ldmatrix.sync.aligned.m8n8.x4.shared.b16 {%0,%1,%2,%3}, [%4];" \
                 : "=r"(r0), "=r"(r1), "=r"(r2), "=r"(r3) : "r"(addr))
#define LDSM_X4_T(r0, r1, r2, r3, addr) \
    asm volatile("ldmatrix.sync.aligned.m8n8.x4.trans.shared.b16 {%0,%1,%2,%3}, [%4];" \
                 : "=r"(r0), "=r"(r1), "=r"(r2), "=r"(r3) : "r"(addr))

#define MMA_F16(d, a0, a1, a2, a3, b0, b1) \
    asm volatile( \
        "mma.sync.aligned.m16n8k16.row.col.f32.f16.f16.f32 " \
        "{%0,%1,%2,%3}, {%4,%5,%6,%7}, {%8,%9}, {%0,%1,%2,%3};\n" \
        : "+f"((d)[0]), "+f"((d)[1]), "+f"((d)[2]), "+f"((d)[3]) \
        : "r"(a0), "r"(a1), "r"(a2), "r"(a3), "r"(b0), "r"(b1))

// ============================================================
// weight prep: W_qkv -> fp16
// ============================================================
__global__ __launch_bounds__(256)
void prep_kernel(const float* __restrict__ Wqkv)
{
    int i = blockIdx.x * 256 + threadIdx.x;
    if (i < CH3 * CHN / 4) {
        float4 v = *(const float4*)(Wqkv + i * 4);
        *(__half2*)(g_wqkvh + i * 4)     = __floats2half2_rn(v.x, v.y);
        *(__half2*)(g_wqkvh + i * 4 + 2) = __floats2half2_rn(v.z, v.w);
    }
}

// ============================================================
// FUSED Sobel+HOG+f2h(x), channel-split 8-way.
// grid (IMH, BATCH), block (32,8). hogwh rows 9..31 zeroed here.
// ============================================================
__global__ __launch_bounds__(256)
void sobel_f2h_kernel(const float* __restrict__ x)
{
    const int tx = threadIdx.x;            // 0..31
    const int ty = threadIdx.y;            // 0..7
    const int h  = blockIdx.x;
    const int b  = blockIdx.y;
    const int w0 = tx * 4;
    const int hm = h > 0 ? h - 1 : 0;
    const int hp = h < IMH - 1 ? h + 1 : IMH - 1;
    const float* xb = x + (long)b * CHN * NPIX;
    __half* xhb = g_xh + (long)b * CHN * NPIX;

    float msum[4] = {0.f, 0.f, 0.f, 0.f};
    float asum[4] = {0.f, 0.f, 0.f, 0.f};

    const int c0 = ty * 24;
    for (int c = c0; c < c0 + 24; c++) {
        const float* pc = xb + (long)c * NPIX;
        float row[3][6];
        const int hrows[3] = {hm, h, hp};
#pragma unroll
        for (int rr = 0; rr < 3; rr++) {
            const float* p = pc + hrows[rr] * IMW + w0;
            float4 cv = *(const float4*)p;
            row[rr][1] = cv.x; row[rr][2] = cv.y; row[rr][3] = cv.z; row[rr][4] = cv.w;
            row[rr][0] = (w0 > 0)       ? __ldg(p - 1) : cv.x;   // replicate
            row[rr][5] = (w0 + 4 < IMW) ? __ldg(p + 4) : cv.w;   // replicate
        }

        __half* xd = xhb + (long)c * NPIX + h * IMW + w0;
        *(__half2*)xd       = __floats2half2_rn(row[1][1], row[1][2]);
        *(__half2*)(xd + 2) = __floats2half2_rn(row[1][3], row[1][4]);

#pragma unroll
        for (int j = 0; j < 4; j++) {
            float dx = (row[0][j+2] - row[0][j] + 2.f*(row[1][j+2] - row[1][j])
                      + row[2][j+2] - row[2][j]) * 0.125f;
            float dy = (row[2][j] - row[0][j] + 2.f*(row[2][j+1] - row[0][j+1])
                      + row[2][j+2] - row[0][j+2]) * 0.125f;
            msum[j] += fast_sqrtf(dx*dx + dy*dy + 1e-6f);
            asum[j] += fast_atan2f(dy, dx + 1e-6f);
        }
    }

    __shared__ float smr[2][8][128];
#pragma unroll
    for (int j = 0; j < 4; j++) {
        smr[0][ty][tx * 4 + j] = msum[j];
        smr[1][ty][tx * 4 + j] = asum[j];
    }
    __syncthreads();

    const int pix = h * IMW + w0;

    // zero hog rows 9..31 (distributed over ty 0..7)
    const __half2 z2 = __half2half2(__float2half(0.f));
    for (int o = NORI + ty; o < KHOG; o += 8) {
        __half* d = g_hogwh + ((long)b * KHOG + o) * NPIX + pix;
        *(__half2*)d       = z2;
        *(__half2*)(d + 2) = z2;
    }

    if (ty == 0) {
        const float binw = PI_F / NORI;
        float mag[4], ang[4];
#pragma unroll
        for (int j = 0; j < 4; j++) {
            int i = tx * 4 + j;
            float m = 0.f, a = 0.f;
#pragma unroll
            for (int q = 0; q < 8; q++) { m += smr[0][q][i]; a += smr[1][q][i]; }
            mag[j] = m * (1.f / CHN);
            a = a * (1.f / CHN);
            ang[j] = a - PI_F * floorf(a / PI_F);
        }
#pragma unroll
        for (int o = 0; o < NORI; o++) {
            float cen = ((float)o + 0.5f) * binw;
            float v0 = 1.f - fabsf(ang[0] - cen) / binw;
            float v1 = 1.f - fabsf(ang[1] - cen) / binw;
            float v2 = 1.f - fabsf(ang[2] - cen) / binw;
            float v3 = 1.f - fabsf(ang[3] - cen) / binw;
            v0 = (v0 > 0.f ? v0 : 0.f) * mag[0];
            v1 = (v1 > 0.f ? v1 : 0.f) * mag[1];
            v2 = (v2 > 0.f ? v2 : 0.f) * mag[2];
            v3 = (v3 > 0.f ? v3 : 0.f) * mag[3];
            __half* d = g_hogwh + ((long)b * KHOG + o) * NPIX + pix;
            *(__half2*)d       = __floats2half2_rn(v0, v1);
            *(__half2*)(d + 2) = __floats2half2_rn(v2, v3);
        }
    }
}

// ============================================================
// fp16 GEMM: BM=64 BN=256 BK=32, 256 thr, warp tile 32x64,
// 4-buf cp.async, 2 CTAs/SM. DUAL-SOURCE B: k-rows >= ksplit are
// streamed from B2 (per-iteration uniform pointer select).
// ============================================================
#define HASZ (64*40)
#define HBSZ (32*264)
__global__ __launch_bounds__(256, 2)
void gemm_h16_kernel(const __half* __restrict__ A, long sA,
                     const __half* __restrict__ B, long sB,
                     const __half* __restrict__ B2, long sB2, int ksplit,
                     void* __restrict__ Cm, long sC,
                     int N, int K, int out_half)
{
    extern __shared__ __half hsmem[];
    __half* As = hsmem;              // NB stages 64x40
    __half* Bs = hsmem + NB * HASZ;  // NB stages 32x264

    const int t = threadIdx.x;
    const int lane = t & 31;
    const int warp = t >> 5;
    const int wm = warp >> 2;
    const int wn = warp & 3;
    const int m0 = blockIdx.y * 64;
    const int n0 = blockIdx.x * 256;
    const __half* Ab  = A  + (long)blockIdx.z * sA;
    const __half* Bb  = B  + (long)blockIdx.z * sB;
    const __half* B2b = B2 + (long)blockIdx.z * sB2;

    const int kc = lane & 3;
    const int lq = lane >> 2;
    const int l15 = lane & 15;
    const int lh8 = (lane >> 4) * 8;

    const int niter = K / 32;

    float acc[2][8][4];
#pragma unroll
    for (int i = 0; i < 2; i++)
#pragma unroll
        for (int j = 0; j < 8; j++)
#pragma unroll
            for (int r = 0; r < 4; r++) acc[i][j][r] = 0.f;

    auto issue_stage = [&](int it) {
        const int stg = it & (NB - 1);
        const int k0 = it * 32;
        cp_async16(smem_u32(&As[stg * HASZ + (t >> 2) * 40 + (t & 3) * 8]),
                   Ab + (long)(m0 + (t >> 2)) * K + k0 + (t & 3) * 8);
        const __half* bbase = (k0 < ksplit)
            ? (Bb + (long)k0 * N)
            : (B2b + (long)(k0 - ksplit) * N);
#pragma unroll
        for (int j = 0; j < 4; j++) {
            int cch = (t & 7) + 8 * j;
            cp_async16(smem_u32(&Bs[stg * HBSZ + (t >> 3) * 264 + cch * 8]),
                       bbase + (long)(t >> 3) * N + n0 + cch * 8);
        }
    };

#pragma unroll
    for (int s = 0; s < 2; s++) {
        if (s < niter) issue_stage(s);
        cp_commit();
    }

    for (int it = 0; it < niter; it++) {
        if (it + 2 < niter) issue_stage(it + 2);
        cp_commit();
        cp_wait2();
        __syncthreads();

        const __half* Ast = As + (it & (NB - 1)) * HASZ;
        const __half* Bst = Bs + (it & (NB - 1)) * HBSZ;

#pragma unroll
        for (int ks = 0; ks < 2; ks++) {
            const int kb = ks * 16;
            uint32_t af[2][4], bf[8][2];
#pragma unroll
            for (int mt = 0; mt < 2; mt++) {
                uint32_t ad = smem_u32(Ast + (wm * 32 + mt * 16 + l15) * 40 + kb + lh8);
                LDSM_X4(af[mt][0], af[mt][1], af[mt][2], af[mt][3], ad);
            }
#pragma unroll
            for (int np = 0; np < 4; np++) {
                int krow = kb + ((lane >> 3) & 1) * 8 + (lane & 7);
                int ncol = wn * 64 + np * 16 + lh8;
                uint32_t bd = smem_u32(Bst + krow * 264 + ncol);
                LDSM_X4_T(bf[np*2][0], bf[np*2][1], bf[np*2+1][0], bf[np*2+1][1], bd);
            }
#pragma unroll
            for (int mt = 0; mt < 2; mt++)
#pragma unroll
                for (int nt = 0; nt < 8; nt++)
                    MMA_F16(acc[mt][nt], af[mt][0], af[mt][1], af[mt][2], af[mt][3],
                            bf[nt][0], bf[nt][1]);
        }
    }

    if (out_half) {
        __half* Cb = (__half*)Cm + (long)blockIdx.z * sC;
#pragma unroll
        for (int mt = 0; mt < 2; mt++) {
            int r = m0 + wm * 32 + mt * 16 + lq;
#pragma unroll
            for (int nt = 0; nt < 8; nt++) {
                int c = n0 + wn * 64 + nt * 8 + kc * 2;
                *(__half2*)(Cb + (long)r * N + c) =
                    __floats2half2_rn(acc[mt][nt][0], acc[mt][nt][1]);
                *(__half2*)(Cb + (long)(r + 8) * N + c) =
                    __floats2half2_rn(acc[mt][nt][2], acc[mt][nt][3]);
            }
        }
    } else {
        float* Cb = (float*)Cm + (long)blockIdx.z * sC;
#pragma unroll
        for (int mt = 0; mt < 2; mt++) {
            int r = m0 + wm * 32 + mt * 16 + lq;
#pragma unroll
            for (int nt = 0; nt < 8; nt++) {
                int c = n0 + wn * 64 + nt * 8 + kc * 2;
                *(float2*)(Cb + (long)r * N + c) =
                    make_float2(acc[mt][nt][0], acc[mt][nt][1]);
                *(float2*)(Cb + (long)(r + 8) * N + c) =
                    make_float2(acc[mt][nt][2], acc[mt][nt][3]);
            }
        }
    }
}

// ============================================================
// attn partial via fp16 MMA, warp layout 3m x 2k:
// 6 warps: wm in {0,1,2} (16 rows), wk in {0,1} (k-half of 32-px chunk).
// Each warp: full n=48 via 3 non-trans LDSM_X4; 6 MMAs.
// Partials per k-half -> attnp slice split*2+wk (NSLICE=32).
// ============================================================
#define HQSZ (48*40)
__global__ __launch_bounds__(192, 4)
void attn_partial_kernel()
{
    extern __shared__ __half hsmem[];
    __half* Qs = hsmem;
    __half* Ks = hsmem + NB * HQSZ;

    const int bh = blockIdx.x;
    const int split = blockIdx.y;
    const int b = bh >> 2, hh = bh & 3;
    const __half* Qg = g_qkvdw + ((long)b * CH3 + hh * HDIM) * NPIX;
    const __half* Kg = g_qkvdw + ((long)b * CH3 + CHN + hh * HDIM) * NPIX;
    const int nbase = split * SPLITLEN;

    const int t = threadIdx.x;
    const int lane = t & 31;
    const int warp = t >> 5;
    const int wm = warp % 3;
    const int wk = warp / 3;           // 0..1
    const int kb = wk * 16;            // fixed k-half within each 32-px chunk
    const int kc = lane & 3;
    const int lq = lane >> 2;
    const int l15 = lane & 15;

    float acc[6][4];
#pragma unroll
    for (int i = 0; i < 6; i++)
#pragma unroll
        for (int r = 0; r < 4; r++) acc[i][r] = 0.f;

    const int niter = SPLITLEN / 32;   // 32

    auto issue_stage = [&](int it) {
        const int stg = it & (NB - 1);
        const int base = nbase + it * 32;
        int r = t >> 2, c4 = t & 3;
        cp_async16(smem_u32(&Qs[stg * HQSZ + r * 40 + c4 * 8]),
                   Qg + (long)r * NPIX + base + c4 * 8);
        cp_async16(smem_u32(&Ks[stg * HQSZ + r * 40 + c4 * 8]),
                   Kg + (long)r * NPIX + base + c4 * 8);
    };

#pragma unroll
    for (int s = 0; s < 2; s++) {
        if (s < niter) issue_stage(s);
        cp_commit();
    }

    // B-fragment address pattern (verified): row = n_t + (lane&7) + ((lane>>4)&1)*8,
    // col = kb + ((lane>>3)&1)*8  -> mats {b0t0,b1t0,b0t1,b1t1}
    const int brow_off = (lane & 7) + ((lane >> 4) & 1) * 8;
    const int bcol = kb + ((lane >> 3) & 1) * 8;

    for (int it = 0; it < niter; it++) {
        if (it + 2 < niter) issue_stage(it + 2);
        cp_commit();
        cp_wait2();
        __syncthreads();

        const __half* Qst = Qs + (it & (NB - 1)) * HQSZ;
        const __half* Kst = Ks + (it & (NB - 1)) * HQSZ;

        uint32_t af[4];
        {
            uint32_t ad = smem_u32(Qst + (wm * 16 + l15) * 40 + kb + (lane >> 4) * 8);
            LDSM_X4(af[0], af[1], af[2], af[3], ad);
        }
#pragma unroll
        for (int nt2 = 0; nt2 < 3; nt2++) {
            uint32_t b0, b1, b2, b3;
            uint32_t bd = smem_u32(Kst + (nt2 * 16 + brow_off) * 40 + bcol);
            LDSM_X4(b0, b1, b2, b3, bd);
            MMA_F16(acc[nt2*2],     af[0], af[1], af[2], af[3], b0, b1);
            MMA_F16(acc[nt2*2 + 1], af[0], af[1], af[2], af[3], b2, b3);
        }
    }

    float* dst = g_attnp + ((long)((bh * NSPLIT + split) * 2 + wk)) * HDIM * HDIM;
    int row = wm * 16 + lq;
#pragma unroll
    for (int j = 0; j < 6; j++) {
        int col = (j >> 1) * 16 + (j & 1) * 8 + kc * 2;
        *(float2*)(dst + row * HDIM + col) = make_float2(acc[j][0], acc[j][1]);
        *(float2*)(dst + (row + 8) * HDIM + col) = make_float2(acc[j][2], acc[j][3]);
    }
}

// ============================================================
// Depthwise 3x3 SAME (zero pad), 2 rows x 8 px/thread, fp16 in/out,
// fused norm partials on q/k. NO hog add (folded into GEMM2).
// grid (1, IMH/32, BATCH*CH3), block (16,16).
// ============================================================
__global__ __launch_bounds__(256)
void dwconv_kernel(const float* __restrict__ Wdw)
{
    const int plane = blockIdx.z;
    const int b  = plane / CH3;
    const int ch = plane - b * CH3;
    const int tx = threadIdx.x;
    const int ty = threadIdx.y;
    const int w0 = tx * 8;
    const int h0 = blockIdx.y * 32 + ty * 2;
    const __half* in = g_qkv + (long)plane * NPIX;
    const float* kw = Wdw + ch * 9;
    float k0 = __ldg(kw+0), k1 = __ldg(kw+1), k2 = __ldg(kw+2);
    float k3 = __ldg(kw+3), k4 = __ldg(kw+4), k5 = __ldg(kw+5);
    float k6 = __ldg(kw+6), k7 = __ldg(kw+7), k8 = __ldg(kw+8);

    float row[4][10];
#pragma unroll
    for (int rr = 0; rr < 4; rr++) {
        int hh = h0 + rr - 1;
        if (hh >= 0 && hh < IMH) {
            const __half* p = in + hh * IMW + w0;
            uint4 u = *(const uint4*)p;
            const __half2* h2 = (const __half2*)&u;
#pragma unroll
            for (int q = 0; q < 4; q++) {
                float2 f = __half22float2(h2[q]);
                row[rr][1 + 2*q] = f.x; row[rr][2 + 2*q] = f.y;
            }
            row[rr][0] = (w0 > 0)       ? __half2float(p[-1]) : 0.f;
            row[rr][9] = (w0 + 8 < IMW) ? __half2float(p[8])  : 0.f;
        } else {
#pragma unroll
            for (int j = 0; j < 10; j++) row[rr][j] = 0.f;
        }
    }

    float out0[8], out1[8];
#pragma unroll
    for (int j = 0; j < 8; j++) {
        out0[j] = k0*row[0][j] + k1*row[0][j+1] + k2*row[0][j+2]
                + k3*row[1][j] + k4*row[1][j+1] + k5*row[1][j+2]
                + k6*row[2][j] + k7*row[2][j+1] + k8*row[2][j+2];
        out1[j] = k0*row[1][j] + k1*row[1][j+1] + k2*row[1][j+2]
                + k3*row[2][j] + k4*row[2][j+1] + k5*row[2][j+2]
                + k6*row[3][j] + k7*row[3][j+1] + k8*row[3][j+2];
    }

    const int pix0 = h0 * IMW + w0;
    const int pix1 = pix0 + IMW;

    __half2 o20[4], o21[4];
#pragma unroll
    for (int q = 0; q < 4; q++) {
        o20[q] = __floats2half2_rn(out0[2*q], out0[2*q+1]);
        o21[q] = __floats2half2_rn(out1[2*q], out1[2*q+1]);
    }
    __half* dst = g_qkvdw + (long)plane * NPIX;
    *(uint4*)(dst + pix0) = *(const uint4*)o20;
    *(uint4*)(dst + pix1) = *(const uint4*)o21;

    if (ch < 2 * CHN) {
        float ss = 0.f;
#pragma unroll
        for (int q = 0; q < 4; q++) {
            float2 f0 = __half22float2(o20[q]);
            float2 f1 = __half22float2(o21[q]);
            ss += f0.x*f0.x + f0.y*f0.y + f1.x*f1.x + f1.y*f1.y;
        }
        const int tid = ty * 16 + tx;
#pragma unroll
        for (int o = 16; o > 0; o >>= 1) ss += __shfl_down_sync(0xffffffffu, ss, o);
        __shared__ float red[8];
        if ((tid & 31) == 0) red[tid >> 5] = ss;
        __syncthreads();
        if (tid == 0) {
            float s = 0.f;
#pragma unroll
            for (int i = 0; i < 8; i++) s += red[i];
            int which = ch / CHN;
            int r = which * (BATCH * CHN) + b * CHN + (ch - which * CHN);
            g_normp[r * 4 + blockIdx.y] = s;
        }
    }
}

// ============================================================
// MERGED: norm finalize + 32-slice reduce + scale + softmax +
// W_proj fold (into g_wfh2, row stride 224) + Z = attn @ W_hog.
// grid (BATCH, NHEADS), 256 threads.
// ============================================================
__global__ __launch_bounds__(256)
void softmax_wf_kernel(const float* __restrict__ Wproj,
                       const float* __restrict__ Whog,
                       const float* __restrict__ temp)
{
    const int b = blockIdx.x, hh = blockIdx.y;
    const int t = threadIdx.x;
    __shared__ float at[HDIM][HDIM];
    __shared__ float nq[HDIM], nk[HDIM];

    if (t < 96) {
        int which = t / HDIM;
        int c = t - which * HDIM;
        int r = which * (BATCH * CHN) + b * CHN + hh * HDIM + c;
        float s = 0.f;
#pragma unroll
        for (int i = 0; i < 4; i++) s += g_normp[r * 4 + i];
        float nv = fmaxf(sqrtf(s), 1e-12f);
        if (which == 0) nq[c] = nv; else nk[c] = nv;
    }
    __syncthreads();

    const float tmp = __ldg(temp + hh);
    const float* pb = g_attnp + (long)(b * NHEADS + hh) * NSLICE * HDIM * HDIM;
    for (int idx = t; idx < HDIM * HDIM; idx += 256) {
        int c = idx / HDIM, d = idx - c * HDIM;
        float s = 0.f;
#pragma unroll
        for (int sp = 0; sp < NSLICE; sp++) s += pb[sp * HDIM * HDIM + idx];
        at[c][d] = s / (nq[c] * nk[d]) * tmp;
    }
    __syncthreads();

    const int warp = t >> 5, lane = t & 31;
    for (int r = warp; r < HDIM; r += 8) {
        float v0 = at[r][lane];
        float v1 = (lane < 16) ? at[r][lane + 32] : -1e30f;
        float mx = fmaxf(v0, v1);
#pragma unroll
        for (int o = 16; o > 0; o >>= 1) mx = fmaxf(mx, __shfl_xor_sync(0xffffffffu, mx, o));
        float e0 = expf(v0 - mx);
        float e1 = (lane < 16) ? expf(v1 - mx) : 0.f;
        float sm = e0 + e1;
#pragma unroll
        for (int o = 16; o > 0; o >>= 1) sm += __shfl_xor_sync(0xffffffffu, sm, o);
        float inv = 1.f / sm;
        at[r][lane] = e0 * inv;
        if (lane < 16) at[r][lane + 32] = e1 * inv;
    }
    __syncthreads();

    // Z[c][o] = sum_d at[c][d] * Whog[hh*48+d][o]
    for (int i = t; i < HDIM * NORI; i += 256) {
        int c = i / NORI, o = i - c * NORI;
        float acc = 0.f;
#pragma unroll 8
        for (int d = 0; d < HDIM; d++)
            acc += at[c][d] * __ldg(Whog + (hh * HDIM + d) * NORI + o);
        g_zf[((long)b * CHN + hh * HDIM + c) * NORI + o] = acc;
    }

    // Wf fold -> g_wfh2 cols hh*48..hh*48+47 (row stride 224)
    for (int i = t; i < CHN * HDIM; i += 256) {
        int e = i / HDIM, d = i - e * HDIM;
        const float* wp = Wproj + (long)e * CHN + hh * HDIM;
        float acc = 0.f;
#pragma unroll
        for (int c2 = 0; c2 < HDIM; c2++) acc += __ldg(wp + c2) * at[c2][d];
        g_wfh2[((long)b * CHN + e) * KEXT + hh * HDIM + d] = __float2half_rn(acc);
    }
}

// ============================================================
// Wfhog = Wproj @ Z -> g_wfh2 cols 192..200; cols 201..223 zero.
// grid (BATCH), 256 threads.
// ============================================================
__global__ __launch_bounds__(256)
void wfhog_kernel(const float* __restrict__ Wproj)
{
    const int b = blockIdx.x;
    const int t = threadIdx.x;
    for (int i = t; i < CHN * KHOG; i += 256) {
        int e = i >> 5, o = i & 31;
        __half val = __float2half(0.f);
        if (o < NORI) {
            float acc = 0.f;
            const float* wp = Wproj + (long)e * CHN;
            const float* zp = g_zf + (long)b * CHN * NORI + o;
#pragma unroll 8
            for (int g = 0; g < CHN; g++)
                acc += __ldg(wp + g) * zp[g * NORI];
            val = __float2half_rn(acc);
        }
        g_wfh2[((long)b * CHN + e) * KEXT + CHN + o] = val;
    }
}

// ============================================================
extern "C" void kernel_launch(void* const* d_in, const int* in_sizes, int n_in,
                              void* d_out, int out_size)
{
    const float* x     = (const float*)d_in[0];
    const float* Wqkv  = (const float*)d_in[1];
    const float* Wdw   = (const float*)d_in[2];
    const float* Whog  = (const float*)d_in[3];
    const float* Wproj = (const float*)d_in[4];
    const float* temp  = (const float*)d_in[5];

    void *p_xh, *p_wqkvh, *p_qkv, *p_qkvdw, *p_wfh2, *p_hogwh;
    cudaGetSymbolAddress(&p_xh,    g_xh);
    cudaGetSymbolAddress(&p_wqkvh, g_wqkvh);
    cudaGetSymbolAddress(&p_qkv,   g_qkv);
    cudaGetSymbolAddress(&p_qkvdw, g_qkvdw);
    cudaGetSymbolAddress(&p_wfh2,  g_wfh2);
    cudaGetSymbolAddress(&p_hogwh, g_hogwh);

    const int gemm_smem = NB * (HASZ + HBSZ) * 2;   // 88064
    const int attn_smem = 2 * NB * HQSZ * 2;        // 30720
    cudaFuncSetAttribute(gemm_h16_kernel,
                         cudaFuncAttributeMaxDynamicSharedMemorySize, gemm_smem);
    cudaFuncSetAttribute(attn_partial_kernel,
                         cudaFuncAttributeMaxDynamicSharedMemorySize, attn_smem);

    // 0) fused Sobel+HOG+f2h(x); W_qkv prep
    sobel_f2h_kernel<<<dim3(IMH, BATCH), dim3(32, 8)>>>(x);
    prep_kernel<<<(CH3*CHN/4 + 255)/256, 256>>>(Wqkv);

    // 1) qkv = W_qkv @ x  (fp16 MMA, fp16 out)
    gemm_h16_kernel<<<dim3(NPIX / 256, CH3 / 64, BATCH), 256, gemm_smem>>>(
        (const __half*)p_wqkvh, 0L,
        (const __half*)p_xh, (long)CHN * NPIX,
        (const __half*)p_xh, (long)CHN * NPIX, CHN,   // no B2 path (ksplit=K)
        p_qkv, (long)CH3 * NPIX,
        NPIX, CHN, 1);

    // 2) depthwise 3x3: q/k/v -> g_qkvdw (+norm partials on q/k)
    dwconv_kernel<<<dim3(1, IMH / 32, BATCH * CH3), dim3(16, 16)>>>(Wdw);

    // 3) q.k^T partial dots (split-K, 2 k-halves/block), fp16 MMA
    attn_partial_kernel<<<dim3(BATCH * NHEADS, NSPLIT), 192, attn_smem>>>();

    // 4) norms + reduce + softmax + W_proj fold + Z (merged)
    softmax_wf_kernel<<<dim3(BATCH, NHEADS), 256>>>(Wproj, Whog, temp);

    // 5) Wfhog = Wproj @ Z -> extra A columns
    wfhog_kernel<<<BATCH, 256>>>(Wproj);

    // 6) out = [Wf | Wfhog] @ [vdw ; hogw]  (K=224, dual-source B)
    gemm_h16_kernel<<<dim3(NPIX / 256, CHN / 64, BATCH), 256, gemm_smem>>>(
        (const __half*)p_wfh2, (long)CHN * KEXT,
        (const __half*)p_qkvdw + (long)2 * CHN * NPIX, (long)CH3 * NPIX,
        (const __half*)p_hogwh, (long)KHOG * NPIX, CHN,
        d_out, (long)CHN * NPIX,
        NPIX, KEXT, 0);
}

// round 17
// speedup vs baseline: 1.2716x; 1.2716x over previous
#include <cuda_runtime.h>
#include <cuda_fp16.h>
#include <math.h>
#include <stdint.h>

#define BATCH 8
#define CHN 192
#define CH3 576
#define IMH 128
#define IMW 128
#define NPIX (IMH*IMW)         // 16384
#define NHEADS 4
#define HDIM 48
#define NORI 9
#define KHOG 32                // padded HOG K
#define NSPLIT 16
#define SPLITLEN (NPIX/NSPLIT) // 1024
#define PI_F 3.14159265358979323846f
#define NB 4                   // pipeline buffers (lookahead 2)

// ---- device scratch (no allocation allowed) ----
__device__ __half g_xh   [BATCH*CHN*NPIX];     // fp16 copy of x
__device__ __half g_wqkvh[CH3*CHN];            // fp16 W_qkv
__device__ __half g_whogh[CHN*KHOG];           // fp16 W_hog padded [192][32]
__device__ __half g_qkv  [BATCH*CH3*NPIX];     // qkv (pre-dwconv), fp16
__device__ __half g_qkvdw[BATCH*CH3*NPIX];     // qkv (post-dwconv), fp16
__device__ __half g_wfh  [BATCH*CHN*CHN];      // folded W_proj*attn, fp16
__device__ __half g_hogwh[BATCH*KHOG*NPIX];    // fp16 hog bin weights (rows 9..31 unused)
__device__ __half g_hogph[BATCH*CHN*NPIX];     // fp16 hog projection
__device__ float g_normp[2*BATCH*CHN*4];
__device__ float g_attnp[BATCH*NHEADS*NSPLIT*HDIM*HDIM];

__device__ __forceinline__ uint32_t smem_u32(const void* p) {
    return (uint32_t)__cvta_generic_to_shared(p);
}
__device__ __forceinline__ void cp_async16(uint32_t dst, const void* src) {
    asm volatile("cp.async.cg.shared.global [%0], [%1], 16;\n" :: "r"(dst), "l"(src));
}
__device__ __forceinline__ void cp_commit() {
    asm volatile("cp.async.commit_group;\n");
}
__device__ __forceinline__ void cp_wait2() {
    asm volatile("cp.async.wait_group 2;\n");
}
__device__ __forceinline__ float fast_sqrtf(float x) {
    float r; asm("sqrt.approx.f32 %0, %1;" : "=f"(r) : "f"(x)); return r;
}
__device__ __forceinline__ float fast_atan2f(float y, float x) {
    float ax = fabsf(x), ay = fabsf(y);
    float mx = fmaxf(ax, ay), mn = fminf(ax, ay);
    float a = __fdividef(mn, mx);
    float s = a * a;
    float r = -0.0117212f;
    r = fmaf(r, s,  0.05265332f);
    r = fmaf(r, s, -0.11643287f);
    r = fmaf(r, s,  0.19354346f);
    r = fmaf(r, s, -0.33262347f);
    r = fmaf(r, s,  0.99997726f);
    r = r * a;
    if (ay > ax) r = 1.57079632679f - r;
    if (x < 0.f) r = PI_F - r;
    return y < 0.f ? -r : r;
}

#define LDSM_X4(r0, r1, r2, r3, addr) \
    asm volatile("ldmatrix.sync.aligned.m8n8.x4.shared.b16 {%0,%1,%2,%3}, [%4];" \
                 : "=r"(r0), "=r"(r1), "=r"(r2), "=r"(r3) : "r"(addr))
#define LDSM_X4_T(r0, r1, r2, r3, addr) \
    asm volatile("ldmatrix.sync.aligned.m8n8.x4.trans.shared.b16 {%0,%1,%2,%3}, [%4];" \
                 : "=r"(r0), "=r"(r1), "=r"(r2), "=r"(r3) : "r"(addr))
#define LDSM_X2(r0, r1, addr) \
    asm volatile("ldmatrix.sync.aligned.m8n8.x2.shared.b16 {%0,%1}, [%2];" \
                 : "=r"(r0), "=r"(r1) : "r"(addr))

#define MMA_F16(d, a0, a1, a2, a3, b0, b1) \
    asm volatile( \
        "mma.sync.aligned.m16n8k16.row.col.f32.f16.f16.f32 " \
        "{%0,%1,%2,%3}, {%4,%5,%6,%7}, {%8,%9}, {%0,%1,%2,%3};\n" \
        : "+f"((d)[0]), "+f"((d)[1]), "+f"((d)[2]), "+f"((d)[3]) \
        : "r"(a0), "r"(a1), "r"(a2), "r"(a3), "r"(b0), "r"(b1))

// ============================================================
// merged weight prep: W_qkv -> fp16; W_hog -> fp16 padded [192][32]
// ============================================================
__global__ __launch_bounds__(256)
void prep_kernel(const float* __restrict__ Wqkv, const float* __restrict__ Whog)
{
    int i = blockIdx.x * 256 + threadIdx.x;
    const int nq4 = CH3 * CHN / 4;
    if (i < nq4) {
        float4 v = *(const float4*)(Wqkv + i * 4);
        *(__half2*)(g_wqkvh + i * 4)     = __floats2half2_rn(v.x, v.y);
        *(__half2*)(g_wqkvh + i * 4 + 2) = __floats2half2_rn(v.z, v.w);
    } else {
        int j = i - nq4;
        if (j < CHN * KHOG) {
            int d = j >> 5, o = j & 31;
            g_whogh[j] = __float2half_rn(o < NORI ? Whog[d * NORI + o] : 0.f);
        }
    }
}

// ============================================================
// FUSED Sobel+HOG+f2h(x), channel-split 8-way.
// grid (IMH, BATCH), block (32,8). Each ty handles 24 channels, 4 px.
// ============================================================
__global__ __launch_bounds__(256)
void sobel_f2h_kernel(const float* __restrict__ x)
{
    const int tx = threadIdx.x;            // 0..31
    const int ty = threadIdx.y;            // 0..7
    const int h  = blockIdx.x;
    const int b  = blockIdx.y;
    const int w0 = tx * 4;
    const int hm = h > 0 ? h - 1 : 0;
    const int hp = h < IMH - 1 ? h + 1 : IMH - 1;
    const float* xb = x + (long)b * CHN * NPIX;
    __half* xhb = g_xh + (long)b * CHN * NPIX;

    float msum[4] = {0.f, 0.f, 0.f, 0.f};
    float asum[4] = {0.f, 0.f, 0.f, 0.f};

    const int c0 = ty * 24;
    for (int c = c0; c < c0 + 24; c++) {
        const float* pc = xb + (long)c * NPIX;
        float row[3][6];
        const int hrows[3] = {hm, h, hp};
#pragma unroll
        for (int rr = 0; rr < 3; rr++) {
            const float* p = pc + hrows[rr] * IMW + w0;
            float4 cv = *(const float4*)p;
            row[rr][1] = cv.x; row[rr][2] = cv.y; row[rr][3] = cv.z; row[rr][4] = cv.w;
            row[rr][0] = (w0 > 0)       ? __ldg(p - 1) : cv.x;   // replicate
            row[rr][5] = (w0 + 4 < IMW) ? __ldg(p + 4) : cv.w;   // replicate
        }

        __half* xd = xhb + (long)c * NPIX + h * IMW + w0;
        *(__half2*)xd       = __floats2half2_rn(row[1][1], row[1][2]);
        *(__half2*)(xd + 2) = __floats2half2_rn(row[1][3], row[1][4]);

#pragma unroll
        for (int j = 0; j < 4; j++) {
            float dx = (row[0][j+2] - row[0][j] + 2.f*(row[1][j+2] - row[1][j])
                      + row[2][j+2] - row[2][j]) * 0.125f;
            float dy = (row[2][j] - row[0][j] + 2.f*(row[2][j+1] - row[0][j+1])
                      + row[2][j+2] - row[0][j+2]) * 0.125f;
            msum[j] += fast_sqrtf(dx*dx + dy*dy + 1e-6f);
            asum[j] += fast_atan2f(dy, dx + 1e-6f);
        }
    }

    __shared__ float smr[2][8][128];
#pragma unroll
    for (int j = 0; j < 4; j++) {
        smr[0][ty][tx * 4 + j] = msum[j];
        smr[1][ty][tx * 4 + j] = asum[j];
    }
    __syncthreads();

    if (ty == 0) {
        const float binw = PI_F / NORI;
        const int pix = h * IMW + w0;
        float mag[4], ang[4];
#pragma unroll
        for (int j = 0; j < 4; j++) {
            int i = tx * 4 + j;
            float m = 0.f, a = 0.f;
#pragma unroll
            for (int q = 0; q < 8; q++) { m += smr[0][q][i]; a += smr[1][q][i]; }
            mag[j] = m * (1.f / CHN);
            a = a * (1.f / CHN);
            ang[j] = a - PI_F * floorf(a / PI_F);
        }
#pragma unroll
        for (int o = 0; o < NORI; o++) {
            float cen = ((float)o + 0.5f) * binw;
            float v0 = 1.f - fabsf(ang[0] - cen) / binw;
            float v1 = 1.f - fabsf(ang[1] - cen) / binw;
            float v2 = 1.f - fabsf(ang[2] - cen) / binw;
            float v3 = 1.f - fabsf(ang[3] - cen) / binw;
            v0 = (v0 > 0.f ? v0 : 0.f) * mag[0];
            v1 = (v1 > 0.f ? v1 : 0.f) * mag[1];
            v2 = (v2 > 0.f ? v2 : 0.f) * mag[2];
            v3 = (v3 > 0.f ? v3 : 0.f) * mag[3];
            __half* d = g_hogwh + ((long)b * KHOG + o) * NPIX + pix;
            *(__half2*)d       = __floats2half2_rn(v0, v1);
            *(__half2*)(d + 2) = __floats2half2_rn(v2, v3);
        }
    }
}

// ============================================================
// fp16 GEMM (round-10 config): BM=64 BN=256 BK=32, 256 thr,
// warp tile 32x64, 4-buf cp.async, 2 CTAs/SM.
// ============================================================
#define HASZ (64*40)
#define HBSZ (32*264)
__global__ __launch_bounds__(256, 2)
void gemm_h16_kernel(const __half* __restrict__ A, long sA,
                     const __half* __restrict__ B, long sB,
                     void* __restrict__ Cm, long sC,
                     int N, int K, int out_half)
{
    extern __shared__ __half hsmem[];
    __half* As = hsmem;              // NB stages 64x40
    __half* Bs = hsmem + NB * HASZ;  // NB stages 32x264

    const int t = threadIdx.x;
    const int lane = t & 31;
    const int warp = t >> 5;
    const int wm = warp >> 2;
    const int wn = warp & 3;
    const int m0 = blockIdx.y * 64;
    const int n0 = blockIdx.x * 256;
    const __half* Ab = A + (long)blockIdx.z * sA;
    const __half* Bb = B + (long)blockIdx.z * sB;

    const int kc = lane & 3;
    const int lq = lane >> 2;
    const int l15 = lane & 15;
    const int lh8 = (lane >> 4) * 8;

    const int niter = K / 32;

    float acc[2][8][4];
#pragma unroll
    for (int i = 0; i < 2; i++)
#pragma unroll
        for (int j = 0; j < 8; j++)
#pragma unroll
            for (int r = 0; r < 4; r++) acc[i][j][r] = 0.f;

    auto issue_stage = [&](int it) {
        const int stg = it & (NB - 1);
        const int k0 = it * 32;
        cp_async16(smem_u32(&As[stg * HASZ + (t >> 2) * 40 + (t & 3) * 8]),
                   Ab + (long)(m0 + (t >> 2)) * K + k0 + (t & 3) * 8);
#pragma unroll
        for (int j = 0; j < 4; j++) {
            int cch = (t & 7) + 8 * j;
            cp_async16(smem_u32(&Bs[stg * HBSZ + (t >> 3) * 264 + cch * 8]),
                       Bb + (long)(k0 + (t >> 3)) * N + n0 + cch * 8);
        }
    };

#pragma unroll
    for (int s = 0; s < 2; s++) {
        if (s < niter) issue_stage(s);
        cp_commit();
    }

    for (int it = 0; it < niter; it++) {
        if (it + 2 < niter) issue_stage(it + 2);
        cp_commit();
        cp_wait2();
        __syncthreads();

        const __half* Ast = As + (it & (NB - 1)) * HASZ;
        const __half* Bst = Bs + (it & (NB - 1)) * HBSZ;

#pragma unroll
        for (int ks = 0; ks < 2; ks++) {
            const int kb = ks * 16;
            uint32_t af[2][4], bf[8][2];
#pragma unroll
            for (int mt = 0; mt < 2; mt++) {
                uint32_t ad = smem_u32(Ast + (wm * 32 + mt * 16 + l15) * 40 + kb + lh8);
                LDSM_X4(af[mt][0], af[mt][1], af[mt][2], af[mt][3], ad);
            }
#pragma unroll
            for (int np = 0; np < 4; np++) {
                int krow = kb + ((lane >> 3) & 1) * 8 + (lane & 7);
                int ncol = wn * 64 + np * 16 + lh8;
                uint32_t bd = smem_u32(Bst + krow * 264 + ncol);
                LDSM_X4_T(bf[np*2][0], bf[np*2][1], bf[np*2+1][0], bf[np*2+1][1], bd);
            }
#pragma unroll
            for (int mt = 0; mt < 2; mt++)
#pragma unroll
                for (int nt = 0; nt < 8; nt++)
                    MMA_F16(acc[mt][nt], af[mt][0], af[mt][1], af[mt][2], af[mt][3],
                            bf[nt][0], bf[nt][1]);
        }
    }

    if (out_half) {
        __half* Cb = (__half*)Cm + (long)blockIdx.z * sC;
#pragma unroll
        for (int mt = 0; mt < 2; mt++) {
            int r = m0 + wm * 32 + mt * 16 + lq;
#pragma unroll
            for (int nt = 0; nt < 8; nt++) {
                int c = n0 + wn * 64 + nt * 8 + kc * 2;
                *(__half2*)(Cb + (long)r * N + c) =
                    __floats2half2_rn(acc[mt][nt][0], acc[mt][nt][1]);
                *(__half2*)(Cb + (long)(r + 8) * N + c) =
                    __floats2half2_rn(acc[mt][nt][2], acc[mt][nt][3]);
            }
        }
    } else {
        float* Cb = (float*)Cm + (long)blockIdx.z * sC;
#pragma unroll
        for (int mt = 0; mt < 2; mt++) {
            int r = m0 + wm * 32 + mt * 16 + lq;
#pragma unroll
            for (int nt = 0; nt < 8; nt++) {
                int c = n0 + wn * 64 + nt * 8 + kc * 2;
                *(float2*)(Cb + (long)r * N + c) =
                    make_float2(acc[mt][nt][0], acc[mt][nt][1]);
                *(float2*)(Cb + (long)(r + 8) * N + c) =
                    make_float2(acc[mt][nt][2], acc[mt][nt][3]);
            }
        }
    }
}

// ============================================================
// attn partial via fp16 MMA: S[bh,split][48][48] = Q_tile @ K_tile^T.
// NSPLIT=16, SPLITLEN=1024 (32 chunk-iters).
// ============================================================
#define HQSZ (48*40)
__global__ __launch_bounds__(192, 4)
void attn_partial_kernel()
{
    extern __shared__ __half hsmem[];
    __half* Qs = hsmem;
    __half* Ks = hsmem + NB * HQSZ;

    const int bh = blockIdx.x;
    const int split = blockIdx.y;
    const int b = bh >> 2, hh = bh & 3;
    const __half* Qg = g_qkvdw + ((long)b * CH3 + hh * HDIM) * NPIX;
    const __half* Kg = g_qkvdw + ((long)b * CH3 + CHN + hh * HDIM) * NPIX;
    const int nbase = split * SPLITLEN;

    const int t = threadIdx.x;
    const int lane = t & 31;
    const int warp = t >> 5;
    const int wm = warp % 3;
    const int wn = warp / 3;
    const int kc = lane & 3;
    const int lq = lane >> 2;
    const int l15 = lane & 15;

    float acc[3][4];
#pragma unroll
    for (int i = 0; i < 3; i++)
#pragma unroll
        for (int r = 0; r < 4; r++) acc[i][r] = 0.f;

    const int niter = SPLITLEN / 32;   // 32

    auto issue_stage = [&](int it) {
        const int stg = it & (NB - 1);
        const int base = nbase + it * 32;
        int r = t >> 2, c4 = t & 3;
        cp_async16(smem_u32(&Qs[stg * HQSZ + r * 40 + c4 * 8]),
                   Qg + (long)r * NPIX + base + c4 * 8);
        cp_async16(smem_u32(&Ks[stg * HQSZ + r * 40 + c4 * 8]),
                   Kg + (long)r * NPIX + base + c4 * 8);
    };

#pragma unroll
    for (int s = 0; s < 2; s++) {
        if (s < niter) issue_stage(s);
        cp_commit();
    }

    for (int it = 0; it < niter; it++) {
        if (it + 2 < niter) issue_stage(it + 2);
        cp_commit();
        cp_wait2();
        __syncthreads();

        const __half* Qst = Qs + (it & (NB - 1)) * HQSZ;
        const __half* Kst = Ks + (it & (NB - 1)) * HQSZ;

#pragma unroll
        for (int ks = 0; ks < 2; ks++) {
            const int kb = ks * 16;
            uint32_t af[4], bf[3][2];
            {
                uint32_t ad = smem_u32(Qst + (wm * 16 + l15) * 40 + kb + (lane >> 4) * 8);
                LDSM_X4(af[0], af[1], af[2], af[3], ad);
            }
#pragma unroll
            for (int nt = 0; nt < 3; nt++) {
                int nrow = wn * 24 + nt * 8 + (l15 & 7);
                int kcol = kb + ((l15 >> 3) & 1) * 8;
                uint32_t bd = smem_u32(Kst + nrow * 40 + kcol);
                LDSM_X2(bf[nt][0], bf[nt][1], bd);
            }
#pragma unroll
            for (int nt = 0; nt < 3; nt++)
                MMA_F16(acc[nt], af[0], af[1], af[2], af[3], bf[nt][0], bf[nt][1]);
        }
    }

    float* dst = g_attnp + ((long)bh * NSPLIT + split) * HDIM * HDIM;
    int row = wm * 16 + lq;
#pragma unroll
    for (int nt = 0; nt < 3; nt++) {
        int col = wn * 24 + nt * 8 + kc * 2;
        *(float2*)(dst + row * HDIM + col) = make_float2(acc[nt][0], acc[nt][1]);
        *(float2*)(dst + (row + 8) * HDIM + col) = make_float2(acc[nt][2], acc[nt][3]);
    }
}

// ============================================================
// Depthwise 3x3 SAME (zero pad), 2 rows x 8 px per thread, fp16 in/out,
// fused hogp add on v, fused norm partials on q/k.
// grid (1, IMH/32, BATCH*CH3), block (16,16).
// ============================================================
__global__ __launch_bounds__(256)
void dwconv_hog_kernel(const float* __restrict__ Wdw)
{
    const int plane = blockIdx.z;
    const int b  = plane / CH3;
    const int ch = plane - b * CH3;
    const int tx = threadIdx.x;            // 0..15
    const int ty = threadIdx.y;            // 0..15
    const int w0 = tx * 8;
    const int h0 = blockIdx.y * 32 + ty * 2;
    const __half* in = g_qkv + (long)plane * NPIX;
    const float* kw = Wdw + ch * 9;
    float k0 = __ldg(kw+0), k1 = __ldg(kw+1), k2 = __ldg(kw+2);
    float k3 = __ldg(kw+3), k4 = __ldg(kw+4), k5 = __ldg(kw+5);
    float k6 = __ldg(kw+6), k7 = __ldg(kw+7), k8 = __ldg(kw+8);

    float row[4][10];
#pragma unroll
    for (int rr = 0; rr < 4; rr++) {
        int hh = h0 + rr - 1;
        if (hh >= 0 && hh < IMH) {
            const __half* p = in + hh * IMW + w0;
            uint4 u = *(const uint4*)p;
            const __half2* h2 = (const __half2*)&u;
#pragma unroll
            for (int q = 0; q < 4; q++) {
                float2 f = __half22float2(h2[q]);
                row[rr][1 + 2*q] = f.x; row[rr][2 + 2*q] = f.y;
            }
            row[rr][0] = (w0 > 0)       ? __half2float(p[-1]) : 0.f;
            row[rr][9] = (w0 + 8 < IMW) ? __half2float(p[8])  : 0.f;
        } else {
#pragma unroll
            for (int j = 0; j < 10; j++) row[rr][j] = 0.f;
        }
    }

    float out0[8], out1[8];
#pragma unroll
    for (int j = 0; j < 8; j++) {
        out0[j] = k0*row[0][j] + k1*row[0][j+1] + k2*row[0][j+2]
                + k3*row[1][j] + k4*row[1][j+1] + k5*row[1][j+2]
                + k6*row[2][j] + k7*row[2][j+1] + k8*row[2][j+2];
        out1[j] = k0*row[1][j] + k1*row[1][j+1] + k2*row[1][j+2]
                + k3*row[2][j] + k4*row[2][j+1] + k5*row[2][j+2]
                + k6*row[3][j] + k7*row[3][j+1] + k8*row[3][j+2];
    }

    const int pix0 = h0 * IMW + w0;
    const int pix1 = pix0 + IMW;
    if (ch >= 2 * CHN) {
        int d = ch - 2 * CHN;
        const __half* hp = g_hogph + ((long)b * CHN + d) * NPIX;
        uint4 u0 = *(const uint4*)(hp + pix0);
        uint4 u1 = *(const uint4*)(hp + pix1);
        const __half2* a0 = (const __half2*)&u0;
        const __half2* a1 = (const __half2*)&u1;
#pragma unroll
        for (int q = 0; q < 4; q++) {
            float2 f0 = __half22float2(a0[q]);
            float2 f1 = __half22float2(a1[q]);
            out0[2*q] += f0.x; out0[2*q+1] += f0.y;
            out1[2*q] += f1.x; out1[2*q+1] += f1.y;
        }
    }

    __half2 o20[4], o21[4];
#pragma unroll
    for (int q = 0; q < 4; q++) {
        o20[q] = __floats2half2_rn(out0[2*q], out0[2*q+1]);
        o21[q] = __floats2half2_rn(out1[2*q], out1[2*q+1]);
    }
    __half* dst = g_qkvdw + (long)plane * NPIX;
    *(uint4*)(dst + pix0) = *(const uint4*)o20;
    *(uint4*)(dst + pix1) = *(const uint4*)o21;

    if (ch < 2 * CHN) {
        float ss = 0.f;
#pragma unroll
        for (int q = 0; q < 4; q++) {
            float2 f0 = __half22float2(o20[q]);
            float2 f1 = __half22float2(o21[q]);
            ss += f0.x*f0.x + f0.y*f0.y + f1.x*f1.x + f1.y*f1.y;
        }
        const int tid = ty * 16 + tx;
#pragma unroll
        for (int o = 16; o > 0; o >>= 1) ss += __shfl_down_sync(0xffffffffu, ss, o);
        __shared__ float red[8];
        if ((tid & 31) == 0) red[tid >> 5] = ss;
        __syncthreads();
        if (tid == 0) {
            float s = 0.f;
#pragma unroll
            for (int i = 0; i < 8; i++) s += red[i];
            int which = ch / CHN;
            int r = which * (BATCH * CHN) + b * CHN + (ch - which * CHN);
            g_normp[r * 4 + blockIdx.y] = s;
        }
    }
}

// ============================================================
// MERGED: norm finalize + split-reduce + scale + softmax + W_proj fold.
// grid (BATCH, NHEADS), 256 threads.
// ============================================================
__global__ __launch_bounds__(256)
void softmax_wf_kernel(const float* __restrict__ Wproj, const float* __restrict__ temp)
{
    const int b = blockIdx.x, hh = blockIdx.y;
    const int t = threadIdx.x;
    __shared__ float at[HDIM][HDIM];
    __shared__ float nq[HDIM], nk[HDIM];

    if (t < 96) {
        int which = t / HDIM;
        int c = t - which * HDIM;
        int r = which * (BATCH * CHN) + b * CHN + hh * HDIM + c;
        float s = 0.f;
#pragma unroll
        for (int i = 0; i < 4; i++) s += g_normp[r * 4 + i];
        float nv = fmaxf(sqrtf(s), 1e-12f);
        if (which == 0) nq[c] = nv; else nk[c] = nv;
    }
    __syncthreads();

    const float tmp = __ldg(temp + hh);
    const float* pb = g_attnp + (long)(b * NHEADS + hh) * NSPLIT * HDIM * HDIM;
    for (int idx = t; idx < HDIM * HDIM; idx += 256) {
        int c = idx / HDIM, d = idx - c * HDIM;
        float s = 0.f;
#pragma unroll
        for (int sp = 0; sp < NSPLIT; sp++) s += pb[sp * HDIM * HDIM + idx];
        at[c][d] = s / (nq[c] * nk[d]) * tmp;
    }
    __syncthreads();

    const int warp = t >> 5, lane = t & 31;
    for (int r = warp; r < HDIM; r += 8) {
        float v0 = at[r][lane];
        float v1 = (lane < 16) ? at[r][lane + 32] : -1e30f;
        float mx = fmaxf(v0, v1);
#pragma unroll
        for (int o = 16; o > 0; o >>= 1) mx = fmaxf(mx, __shfl_xor_sync(0xffffffffu, mx, o));
        float e0 = expf(v0 - mx);
        float e1 = (lane < 16) ? expf(v1 - mx) : 0.f;
        float sm = e0 + e1;
#pragma unroll
        for (int o = 16; o > 0; o >>= 1) sm += __shfl_xor_sync(0xffffffffu, sm, o);
        float inv = 1.f / sm;
        at[r][lane] = e0 * inv;
        if (lane < 16) at[r][lane + 32] = e1 * inv;
    }
    __syncthreads();

    for (int i = t; i < CHN * HDIM; i += 256) {
        int e = i / HDIM, d = i - e * HDIM;
        const float* wp = Wproj + (long)e * CHN + hh * HDIM;
        float acc = 0.f;
#pragma unroll
        for (int c2 = 0; c2 < HDIM; c2++) acc += __ldg(wp + c2) * at[c2][d];
        g_wfh[((long)b * CHN + e) * CHN + hh * HDIM + d] = __float2half_rn(acc);
    }
}

// ============================================================
extern "C" void kernel_launch(void* const* d_in, const int* in_sizes, int n_in,
                              void* d_out, int out_size)
{
    const float* x     = (const float*)d_in[0];
    const float* Wqkv  = (const float*)d_in[1];
    const float* Wdw   = (const float*)d_in[2];
    const float* Whog  = (const float*)d_in[3];
    const float* Wproj = (const float*)d_in[4];
    const float* temp  = (const float*)d_in[5];

    void *p_xh, *p_wqkvh, *p_whogh, *p_qkv, *p_qkvdw, *p_wfh, *p_hogwh, *p_hogph;
    cudaGetSymbolAddress(&p_xh,    g_xh);
    cudaGetSymbolAddress(&p_wqkvh, g_wqkvh);
    cudaGetSymbolAddress(&p_whogh, g_whogh);
    cudaGetSymbolAddress(&p_qkv,   g_qkv);
    cudaGetSymbolAddress(&p_qkvdw, g_qkvdw);
    cudaGetSymbolAddress(&p_wfh,   g_wfh);
    cudaGetSymbolAddress(&p_hogwh, g_hogwh);
    cudaGetSymbolAddress(&p_hogph, g_hogph);

    const int gemm_smem = NB * (HASZ + HBSZ) * 2;   // 88064
    const int attn_smem = 2 * NB * HQSZ * 2;        // 30720
    cudaFuncSetAttribute(gemm_h16_kernel,
                         cudaFuncAttributeMaxDynamicSharedMemorySize, gemm_smem);
    cudaFuncSetAttribute(attn_partial_kernel,
                         cudaFuncAttributeMaxDynamicSharedMemorySize, attn_smem);

    // 0) fused Sobel+HOG+f2h(x); merged weight prep
    sobel_f2h_kernel<<<dim3(IMH, BATCH), dim3(32, 8)>>>(x);
    prep_kernel<<<(CH3*CHN/4 + CHN*KHOG + 255)/256, 256>>>(Wqkv, Whog);

    // 1) qkv = W_qkv @ x  (fp16 MMA, fp16 out)
    gemm_h16_kernel<<<dim3(NPIX / 256, CH3 / 64, BATCH), 256, gemm_smem>>>(
        (const __half*)p_wqkvh, 0L,
        (const __half*)p_xh, (long)CHN * NPIX,
        p_qkv, (long)CH3 * NPIX,
        NPIX, CHN, 1);

    // 2) hogp = W_hog(padded) @ hogw  (fp16 GEMM, K=32)
    gemm_h16_kernel<<<dim3(NPIX / 256, CHN / 64, BATCH), 256, gemm_smem>>>(
        (const __half*)p_whogh, 0L,
        (const __half*)p_hogwh, (long)KHOG * NPIX,
        p_hogph, (long)CHN * NPIX,
        NPIX, KHOG, 1);

    // 3) depthwise 3x3 (+hogp add on v, +norm partials on q/k), 2 rows/thread
    dwconv_hog_kernel<<<dim3(1, IMH / 32, BATCH * CH3), dim3(16, 16)>>>(Wdw);

    // 4) q.k^T partial dots (split-K), fp16 MMA
    attn_partial_kernel<<<dim3(BATCH * NHEADS, NSPLIT), 192, attn_smem>>>();

    // 5) norms + reduce + softmax + W_proj fold (merged)
    softmax_wf_kernel<<<dim3(BATCH, NHEADS), 256>>>(Wproj, temp);

    // 6) out = Wf @ v  (fp16 MMA, fp32 out)
    gemm_h16_kernel<<<dim3(NPIX / 256, CHN / 64, BATCH), 256, gemm_smem>>>(
        (const __half*)p_wfh, (long)CHN * CHN,
        (const __half*)p_qkvdw + (long)2 * CHN * NPIX, (long)CH3 * NPIX,
        d_out, (long)CHN * NPIX,
        NPIX, CHN, 0);
}